// round 7
// baseline (speedup 1.0000x reference)
#include <cuda_runtime.h>
#include <cstdint>

// Problem constants (fixed by dataset setup_inputs)
#define NE 400000          // edges
#define NH 8               // heads
#define ND 32              // head dim
#define MAX_NODES 50000    // n_nodes
#define SEG (MAX_NODES * NH)
#define C 256              // edges per block (= blockDim.x)

// Scratch (allocation-free rule: __device__ globals). Only boundary edges
// (~3% of all edges) ever touch these.
__device__ float g_score[NE * NH];  // exp scores for boundary edges
__device__ float g_sum[SEG];        // global sums for boundary segments
__device__ int   g_blist[NE];       // compact list of boundary edge ids
__device__ int   g_bcount;          // its length

// ---------------------------------------------------------------------------
// Fused kernel: block b owns edges [b*C, b*C+C).
//  Phase 1: warp-per-edge coalesced score + exp -> smem.
//  Phase 2: slice leaders (local pos 0 or index change) scan their slice,
//           compute the sum; interior leaders store the RECIPROCAL into every
//           slot of the slice (kills per-edge divides and phase-3 search);
//           boundary leaders atomicAdd raw sums into g_sum.
//  Phase 3: interior edges: out = exp * rsum. boundary edges: spill exp to
//           g_score and append edge id to g_blist (warp-aggregated atomic).
//  Barriers: all __syncthreads() are convergent.
// ---------------------------------------------------------------------------
__global__ void __launch_bounds__(256, 6) fused_kernel(
    const float* __restrict__ q,
    const float* __restrict__ k,
    const float* __restrict__ attn,
    const int*   __restrict__ index,
    float* __restrict__ out)
{
    __shared__ float4 s_attn[2 * NH * 8];                // 2 KB
    __shared__ __align__(16) float s_sc[C][NH];          // 8 KB exp scores
    __shared__ __align__(16) float s_sum[C][NH];         // 8 KB per-edge rsum
    __shared__ int s_idx[C + 2];  // s_idx[j+1] = index[s+j]; [0]=prev, [C+1]=next

    const int tid = threadIdx.x;
    const int s   = blockIdx.x * C;

    // attn to smem: s_attn[h*8+r] = a_q[h][4r..], +64 = a_k.
    {
        const float4* a4 = (const float4*)attn;
        for (int i = tid; i < NH * 16; i += 256) {
            int h = i >> 4, j = i & 15;
            if (j < 8) s_attn[h * 8 + j] = a4[i];
            else       s_attn[64 + h * 8 + (j - 8)] = a4[i];
        }
    }
    // index slice (+ neighbors for boundary detection)
    {
        int e = s + tid;
        s_idx[tid + 1] = (e < NE) ? index[e] : (-2 - tid);  // distinct sentinels
        if (tid == 0) s_idx[0]     = (s > 0)      ? index[s - 1] : -1;
        if (tid == 1) s_idx[C + 1] = (s + C < NE) ? index[s + C] : -1;
    }
    __syncthreads();

    // ---------------- Phase 1: scores ----------------
    const int lane = tid & 31;
    const int w    = tid >> 5;        // warp 0..7, owns local edges [w*32, w*32+32)
    const int g    = lane >> 3;       // head group (heads g and g+4)
    const int r    = lane & 7;        // quad within head

    const float4 aq0 = s_attn[g * 8 + r];
    const float4 aq1 = s_attn[(g + 4) * 8 + r];
    const float4 ak0 = s_attn[64 + g * 8 + r];
    const float4 ak1 = s_attn[64 + (g + 4) * 8 + r];

#pragma unroll 2
    for (int i = 0; i < 32; i++) {
        int le = w * 32 + i;
        int e  = s + le;
        if (e >= NE) break;   // uniform across the warp; no barriers inside

        const float4* __restrict__ q4 = (const float4*)q + (size_t)e * 64;
        const float4* __restrict__ k4 = (const float4*)k + (size_t)e * 64;
        float4 qa = q4[lane];
        float4 qb = q4[32 + lane];
        float4 ka = k4[lane];
        float4 kb = k4[32 + lane];

        float acc0 = qa.x * aq0.x;
        acc0 = fmaf(qa.y, aq0.y, acc0);
        acc0 = fmaf(qa.z, aq0.z, acc0);
        acc0 = fmaf(qa.w, aq0.w, acc0);
        acc0 = fmaf(ka.x, ak0.x, acc0);
        acc0 = fmaf(ka.y, ak0.y, acc0);
        acc0 = fmaf(ka.z, ak0.z, acc0);
        acc0 = fmaf(ka.w, ak0.w, acc0);

        float acc1 = qb.x * aq1.x;
        acc1 = fmaf(qb.y, aq1.y, acc1);
        acc1 = fmaf(qb.z, aq1.z, acc1);
        acc1 = fmaf(qb.w, aq1.w, acc1);
        acc1 = fmaf(kb.x, ak1.x, acc1);
        acc1 = fmaf(kb.y, ak1.y, acc1);
        acc1 = fmaf(kb.z, ak1.z, acc1);
        acc1 = fmaf(kb.w, ak1.w, acc1);

#pragma unroll
        for (int o = 4; o >= 1; o >>= 1) {
            acc0 += __shfl_xor_sync(0xFFFFFFFFu, acc0, o);
            acc1 += __shfl_xor_sync(0xFFFFFFFFu, acc1, o);
        }

        float e0 = __expf(fmaxf(acc0, 0.0f));   // head g   (valid on leaders)
        float e1 = __expf(fmaxf(acc1, 0.0f));   // head g+4 (valid on leaders)

        int src = (lane & 3) * 8;
        float vlo = __shfl_sync(0xFFFFFFFFu, e0, src);
        float vhi = __shfl_sync(0xFFFFFFFFu, e1, src);

        if (lane < 4)                    s_sc[le][lane]           = vlo;
        else if (lane >= 8 && lane < 12) s_sc[le][(lane - 8) + 4] = vhi;
    }
    __syncthreads();

    // ---------------- Phase 2: slice sums -> reciprocals ----------------
    const int t = tid;
    const int e = s + t;
    const bool valid = (e < NE);
    const int  n     = s_idx[t + 1];              // sentinel if !valid
    // local pos 0 is always a slice start (segment may continue from prev chunk)
    const bool isStart = valid && (t == 0 || s_idx[t] != n);
    const bool bnd     = valid && ((s_idx[0] == n) || (s_idx[C + 1] == n));

    if (isStart) {
        float4 a = make_float4(0.f, 0.f, 0.f, 0.f);
        float4 b = make_float4(0.f, 0.f, 0.f, 0.f);
        int j = t;
        while (j < C && s_idx[j + 1] == n) {
            float4 x = *(const float4*)&s_sc[j][0];
            float4 y = *(const float4*)&s_sc[j][4];
            a.x += x.x; a.y += x.y; a.z += x.z; a.w += x.w;
            b.x += y.x; b.y += y.y; b.z += y.z; b.w += y.w;
            j++;
        }
        if (bnd) {
            float* gs = &g_sum[n * NH];
            atomicAdd(gs + 0, a.x); atomicAdd(gs + 1, a.y);
            atomicAdd(gs + 2, a.z); atomicAdd(gs + 3, a.w);
            atomicAdd(gs + 4, b.x); atomicAdd(gs + 5, b.y);
            atomicAdd(gs + 6, b.z); atomicAdd(gs + 7, b.w);
        } else {
            // reciprocal once per segment; broadcast into each slot of slice
            float4 ra, rb;
            ra.x = __frcp_rn(a.x); ra.y = __frcp_rn(a.y);
            ra.z = __frcp_rn(a.z); ra.w = __frcp_rn(a.w);
            rb.x = __frcp_rn(b.x); rb.y = __frcp_rn(b.y);
            rb.z = __frcp_rn(b.z); rb.w = __frcp_rn(b.w);
            for (int j2 = t; j2 < j; j2++) {
                *(float4*)&s_sum[j2][0] = ra;
                *(float4*)&s_sum[j2][4] = rb;
            }
        }
    }
    __syncthreads();   // single convergent barrier

    // ---------------- Phase 3: output (predicated, no barriers) ----------
    float4 x, y;
    if (valid) {
        x = *(const float4*)&s_sc[t][0];
        y = *(const float4*)&s_sc[t][4];
    }
    const bool doBnd = valid && bnd;
    // warp-aggregated append of boundary edges to the compact list
    unsigned m = __ballot_sync(0xFFFFFFFFu, doBnd);
    if (doBnd) {
        int leader = __ffs(m) - 1;
        int base = 0;
        if (lane == leader) base = atomicAdd(&g_bcount, __popc(m));
        base = __shfl_sync(m, base, leader);
        int pos = base + __popc(m & ((1u << lane) - 1u));
        g_blist[pos] = e;
        float4* gp = (float4*)g_score + (size_t)e * 2;
        gp[0] = x; gp[1] = y;
    } else if (valid) {
        float4 ra = *(const float4*)&s_sum[t][0];
        float4 rb = *(const float4*)&s_sum[t][4];
        float4 o0, o1;
        o0.x = x.x * ra.x; o0.y = x.y * ra.y; o0.z = x.z * ra.z; o0.w = x.w * ra.w;
        o1.x = y.x * rb.x; o1.y = y.y * rb.y; o1.z = y.z * rb.z; o1.w = y.w * rb.w;
        float4* op = (float4*)out + (size_t)e * 2;
        op[0] = o0; op[1] = o1;
    }
}

// ---------------------------------------------------------------------------
// Fixup: grid-stride over the compact boundary list (~3% of edges).
// ---------------------------------------------------------------------------
__global__ void __launch_bounds__(256) fixup_kernel(
    const int* __restrict__ index,
    float* __restrict__ out)
{
    const int total  = g_bcount;
    const int stride = gridDim.x * blockDim.x;
    for (int i = blockIdx.x * blockDim.x + threadIdx.x; i < total; i += stride) {
        int e = g_blist[i];
        int n = index[e];
        const float4* sp = (const float4*)g_score + (size_t)e * 2;
        const float4* dp = (const float4*)(g_sum + (size_t)n * NH);
        float4 x = sp[0], y = sp[1];
        float4 da = dp[0], db = dp[1];
        float4 o0, o1;
        o0.x = x.x / da.x; o0.y = x.y / da.y; o0.z = x.z / da.z; o0.w = x.w / da.w;
        o1.x = y.x / db.x; o1.y = y.y / db.y; o1.z = y.z / db.z; o1.w = y.w / db.w;
        float4* op = (float4*)out + (size_t)e * 2;
        op[0] = o0; op[1] = o1;
    }
}

// ---------------------------------------------------------------------------
extern "C" void kernel_launch(void* const* d_in, const int* in_sizes, int n_in,
                              void* d_out, int out_size)
{
    const float* q     = (const float*)d_in[0];
    const float* k     = (const float*)d_in[1];
    const float* attn  = (const float*)d_in[2];
    const int*   index = (const int*)d_in[3];
    float* out = (float*)d_out;

    (void)in_sizes; (void)n_in; (void)out_size;

    // Zero boundary-segment sums + list counter (graph memset nodes).
    void* p = nullptr;
    cudaGetSymbolAddress(&p, g_sum);
    cudaMemsetAsync(p, 0, (size_t)SEG * sizeof(float));
    cudaGetSymbolAddress(&p, g_bcount);
    cudaMemsetAsync(p, 0, sizeof(int));

    const int nblk = (NE + C - 1) / C;   // 1563
    fused_kernel<<<nblk, 256>>>(q, k, attn, index, out);
    fixup_kernel<<<132, 256>>>(index, out);
}

// round 9
// speedup vs baseline: 1.0751x; 1.0751x over previous
#include <cuda_runtime.h>
#include <cstdint>

// Problem constants (fixed by dataset setup_inputs)
#define NE 400000          // edges
#define NH 8               // heads
#define ND 32              // head dim
#define MAX_NODES 50000    // n_nodes

#define EH (NE * NH)       // 3,200,000 (e,h) pairs
#define SEG (MAX_NODES * NH)

// Scratch (allocation-free rule: __device__ globals)
__device__ float g_score[EH];   // 12.8 MB  (holds exp(relu(dot)))
__device__ float g_sum[SEG];    // 1.6 MB   (per (node,head) sum of exps)

// ---------------------------------------------------------------------------
// 1) Warp-cooperative: warp w handles edge w, all 8 heads. (R3-passing kernel)
//    Lane l: group g = l>>3 (heads g, g+4), r = l&7 (quad d in [4r,4r+4)).
//    Fully coalesced q/k loads; shuffle-reduce; coalesced STG + REDG epilogue.
// ---------------------------------------------------------------------------
__global__ void __launch_bounds__(256) score_kernel(
    const float* __restrict__ q,
    const float* __restrict__ k,
    const float* __restrict__ attn,
    const int*   __restrict__ index)
{
    __shared__ float4 s_attn[2 * NH * 8];   // 128 float4 = 2KB
    {
        const float4* a4 = (const float4*)attn;
        for (int i = threadIdx.x; i < NH * 16; i += blockDim.x) {
            int h = i >> 4;
            int j = i & 15;
            if (j < 8) s_attn[h * 8 + j] = a4[i];            // aq
            else       s_attn[64 + h * 8 + (j - 8)] = a4[i]; // ak
        }
    }
    __syncthreads();

    const int lane = threadIdx.x & 31;
    const int warp = (blockIdx.x * blockDim.x + threadIdx.x) >> 5;  // edge id
    if (warp >= NE) return;

    const int g = lane >> 3;          // group 0..3
    const int r = lane & 7;           // quad index within head

    const float4* __restrict__ q4 = (const float4*)q + (size_t)warp * 64;
    const float4* __restrict__ k4 = (const float4*)k + (size_t)warp * 64;

    float4 qa = q4[lane];             // head g,   quad r
    float4 qb = q4[32 + lane];        // head g+4, quad r
    float4 ka = k4[lane];
    float4 kb = k4[32 + lane];

    float4 aq0 = s_attn[g * 8 + r];
    float4 aq1 = s_attn[(g + 4) * 8 + r];
    float4 ak0 = s_attn[64 + g * 8 + r];
    float4 ak1 = s_attn[64 + (g + 4) * 8 + r];

    float acc0 = qa.x * aq0.x;
    acc0 = fmaf(qa.y, aq0.y, acc0);
    acc0 = fmaf(qa.z, aq0.z, acc0);
    acc0 = fmaf(qa.w, aq0.w, acc0);
    acc0 = fmaf(ka.x, ak0.x, acc0);
    acc0 = fmaf(ka.y, ak0.y, acc0);
    acc0 = fmaf(ka.z, ak0.z, acc0);
    acc0 = fmaf(ka.w, ak0.w, acc0);

    float acc1 = qb.x * aq1.x;
    acc1 = fmaf(qb.y, aq1.y, acc1);
    acc1 = fmaf(qb.z, aq1.z, acc1);
    acc1 = fmaf(qb.w, aq1.w, acc1);
    acc1 = fmaf(kb.x, ak1.x, acc1);
    acc1 = fmaf(kb.y, ak1.y, acc1);
    acc1 = fmaf(kb.z, ak1.z, acc1);
    acc1 = fmaf(kb.w, ak1.w, acc1);

#pragma unroll
    for (int o = 4; o >= 1; o >>= 1) {
        acc0 += __shfl_xor_sync(0xFFFFFFFFu, acc0, o);
        acc1 += __shfl_xor_sync(0xFFFFFFFFu, acc1, o);
    }

    float e0 = __expf(fmaxf(acc0, 0.0f));   // head g     (valid on leaders)
    float e1 = __expf(fmaxf(acc1, 0.0f));   // head g + 4 (valid on leaders)

    int src = (lane & 3) * 8;
    float v_lo = __shfl_sync(0xFFFFFFFFu, e0, src);
    float v_hi = __shfl_sync(0xFFFFFFFFu, e1, src);

    bool lo = (lane < 4);
    bool hi = (lane >= 8 && lane < 12);
    if (lo | hi) {
        int head = (lane & 3) + (hi ? 4 : 0);
        float v  = hi ? v_hi : v_lo;
        int node = index[warp];                       // uniform within warp
        g_score[(size_t)warp * NH + head] = v;        // coalesced 8-lane STG
        atomicAdd(&g_sum[node * NH + head], v);       // coalesced 8-lane REDG
    }
}

// ---------------------------------------------------------------------------
// 2) out[e,h] = exp_score[e,h] * rcp(seg_sum[index[e],h])
//    Two edges per thread (doubles MLP), rcp+mul instead of divide.
// ---------------------------------------------------------------------------
__global__ void __launch_bounds__(256) norm_kernel(
    const int*  __restrict__ index,
    float*      __restrict__ out)
{
    int t  = blockIdx.x * blockDim.x + threadIdx.x;
    int e0 = t * 2;
    if (e0 >= NE) return;

    int n0 = index[e0];
    int n1 = index[e0 + 1];           // NE even => e0+1 < NE always

    const float4* __restrict__ s4 = (const float4*)g_score + (size_t)e0 * 2;
    const float4* __restrict__ da = (const float4*)(g_sum + (size_t)n0 * NH);
    const float4* __restrict__ db = (const float4*)(g_sum + (size_t)n1 * NH);

    float4 x0 = s4[0], x1 = s4[1], x2 = s4[2], x3 = s4[3];
    float4 d0 = da[0], d1 = da[1];
    float4 d2 = db[0], d3 = db[1];

    float4 o0, o1, o2, o3;
    o0.x = x0.x * __frcp_rn(d0.x); o0.y = x0.y * __frcp_rn(d0.y);
    o0.z = x0.z * __frcp_rn(d0.z); o0.w = x0.w * __frcp_rn(d0.w);
    o1.x = x1.x * __frcp_rn(d1.x); o1.y = x1.y * __frcp_rn(d1.y);
    o1.z = x1.z * __frcp_rn(d1.z); o1.w = x1.w * __frcp_rn(d1.w);
    o2.x = x2.x * __frcp_rn(d2.x); o2.y = x2.y * __frcp_rn(d2.y);
    o2.z = x2.z * __frcp_rn(d2.z); o2.w = x2.w * __frcp_rn(d2.w);
    o3.x = x3.x * __frcp_rn(d3.x); o3.y = x3.y * __frcp_rn(d3.y);
    o3.z = x3.z * __frcp_rn(d3.z); o3.w = x3.w * __frcp_rn(d3.w);

    float4* __restrict__ out4 = (float4*)out + (size_t)e0 * 2;
    out4[0] = o0;
    out4[1] = o1;
    out4[2] = o2;
    out4[3] = o3;
}

// ---------------------------------------------------------------------------
extern "C" void kernel_launch(void* const* d_in, const int* in_sizes, int n_in,
                              void* d_out, int out_size)
{
    const float* q     = (const float*)d_in[0];
    const float* k     = (const float*)d_in[1];
    const float* attn  = (const float*)d_in[2];
    const int*   index = (const int*)d_in[3];
    float* out = (float*)d_out;

    (void)in_sizes; (void)n_in; (void)out_size;

    // Zero per-segment sums via a graph memset node.
    void* sum_ptr = nullptr;
    cudaGetSymbolAddress(&sum_ptr, g_sum);
    cudaMemsetAsync(sum_ptr, 0, (size_t)SEG * sizeof(float));

    // one warp per edge: NE warps = NE*32 threads, 256/block
    score_kernel<<<(NE * 32 + 255) / 256, 256>>>(q, k, attn, index);
    // two edges per thread
    norm_kernel<<<(NE / 2 + 255) / 256, 256>>>(index, out);
}

// round 10
// speedup vs baseline: 1.0966x; 1.0200x over previous
#include <cuda_runtime.h>
#include <cstdint>

// Problem constants (fixed by dataset setup_inputs)
#define NE 400000          // edges
#define NH 8               // heads
#define ND 32              // head dim
#define MAX_NODES 50000    // n_nodes

#define EH (NE * NH)       // 3,200,000 (e,h) pairs
#define SEG (MAX_NODES * NH)

// Scratch (allocation-free rule: __device__ globals)
__device__ float g_score[EH];   // 12.8 MB  (holds exp(relu(dot)))
__device__ float g_sum[SEG];    // 1.6 MB   (per (node,head) sum of exps)

// ---------------------------------------------------------------------------
// 1) Warp-cooperative: warp w handles edge w, all 8 heads. (R3-passing kernel)
//    Lane l: group g = l>>3 (heads g, g+4), r = l&7 (quad d in [4r,4r+4)).
//    Fully coalesced q/k loads; shuffle-reduce; coalesced STG + REDG epilogue.
// ---------------------------------------------------------------------------
__global__ void __launch_bounds__(256) score_kernel(
    const float* __restrict__ q,
    const float* __restrict__ k,
    const float* __restrict__ attn,
    const int*   __restrict__ index)
{
    __shared__ float4 s_attn[2 * NH * 8];   // 128 float4 = 2KB
    {
        const float4* a4 = (const float4*)attn;
        for (int i = threadIdx.x; i < NH * 16; i += blockDim.x) {
            int h = i >> 4;
            int j = i & 15;
            if (j < 8) s_attn[h * 8 + j] = a4[i];            // aq
            else       s_attn[64 + h * 8 + (j - 8)] = a4[i]; // ak
        }
    }
    __syncthreads();

    const int lane = threadIdx.x & 31;
    const int warp = (blockIdx.x * blockDim.x + threadIdx.x) >> 5;  // edge id
    if (warp >= NE) return;

    const int g = lane >> 3;          // group 0..3
    const int r = lane & 7;           // quad index within head

    const float4* __restrict__ q4 = (const float4*)q + (size_t)warp * 64;
    const float4* __restrict__ k4 = (const float4*)k + (size_t)warp * 64;

    float4 qa = q4[lane];             // head g,   quad r
    float4 qb = q4[32 + lane];        // head g+4, quad r
    float4 ka = k4[lane];
    float4 kb = k4[32 + lane];

    float4 aq0 = s_attn[g * 8 + r];
    float4 aq1 = s_attn[(g + 4) * 8 + r];
    float4 ak0 = s_attn[64 + g * 8 + r];
    float4 ak1 = s_attn[64 + (g + 4) * 8 + r];

    float acc0 = qa.x * aq0.x;
    acc0 = fmaf(qa.y, aq0.y, acc0);
    acc0 = fmaf(qa.z, aq0.z, acc0);
    acc0 = fmaf(qa.w, aq0.w, acc0);
    acc0 = fmaf(ka.x, ak0.x, acc0);
    acc0 = fmaf(ka.y, ak0.y, acc0);
    acc0 = fmaf(ka.z, ak0.z, acc0);
    acc0 = fmaf(ka.w, ak0.w, acc0);

    float acc1 = qb.x * aq1.x;
    acc1 = fmaf(qb.y, aq1.y, acc1);
    acc1 = fmaf(qb.z, aq1.z, acc1);
    acc1 = fmaf(qb.w, aq1.w, acc1);
    acc1 = fmaf(kb.x, ak1.x, acc1);
    acc1 = fmaf(kb.y, ak1.y, acc1);
    acc1 = fmaf(kb.z, ak1.z, acc1);
    acc1 = fmaf(kb.w, ak1.w, acc1);

#pragma unroll
    for (int o = 4; o >= 1; o >>= 1) {
        acc0 += __shfl_xor_sync(0xFFFFFFFFu, acc0, o);
        acc1 += __shfl_xor_sync(0xFFFFFFFFu, acc1, o);
    }

    float e0 = __expf(fmaxf(acc0, 0.0f));   // head g     (valid on leaders)
    float e1 = __expf(fmaxf(acc1, 0.0f));   // head g + 4 (valid on leaders)

    int src = (lane & 3) * 8;
    float v_lo = __shfl_sync(0xFFFFFFFFu, e0, src);
    float v_hi = __shfl_sync(0xFFFFFFFFu, e1, src);

    bool lo = (lane < 4);
    bool hi = (lane >= 8 && lane < 12);
    if (lo | hi) {
        int head = (lane & 3) + (hi ? 4 : 0);
        float v  = hi ? v_hi : v_lo;
        int node = index[warp];                       // uniform within warp
        g_score[(size_t)warp * NH + head] = v;        // coalesced 8-lane STG
        atomicAdd(&g_sum[node * NH + head], v);       // coalesced 8-lane REDG
    }
}

// ---------------------------------------------------------------------------
// 2) out[e, 4h-half] = score / seg_sum — one thread per (edge, head-half).
//    800k light threads (≈20 regs): 2x the in-flight loads of the 1-edge/
//    thread version. Blocks run in REVERSE edge order so the score lines most
//    recently written by score_kernel (still L2-resident) are read first.
// ---------------------------------------------------------------------------
__global__ void __launch_bounds__(256) norm_kernel(
    const int*  __restrict__ index,
    float*      __restrict__ out)
{
    // reverse block order
    int t = (gridDim.x - 1 - blockIdx.x) * blockDim.x + threadIdx.x;
    if (t >= NE * 2) return;

    int e    = t >> 1;          // edge
    int half = t & 1;           // 0: heads 0-3, 1: heads 4-7

    int node = index[e];
    float4 x = ((const float4*)g_score)[(size_t)e * 2 + half];
    float4 d = ((const float4*)(g_sum + (size_t)node * NH))[half];

    float4 o;
    o.x = x.x / d.x;
    o.y = x.y / d.y;
    o.z = x.z / d.z;
    o.w = x.w / d.w;

    ((float4*)out)[(size_t)e * 2 + half] = o;
}

// ---------------------------------------------------------------------------
extern "C" void kernel_launch(void* const* d_in, const int* in_sizes, int n_in,
                              void* d_out, int out_size)
{
    const float* q     = (const float*)d_in[0];
    const float* k     = (const float*)d_in[1];
    const float* attn  = (const float*)d_in[2];
    const int*   index = (const int*)d_in[3];
    float* out = (float*)d_out;

    (void)in_sizes; (void)n_in; (void)out_size;

    // Zero per-segment sums via a graph memset node.
    void* sum_ptr = nullptr;
    cudaGetSymbolAddress(&sum_ptr, g_sum);
    cudaMemsetAsync(sum_ptr, 0, (size_t)SEG * sizeof(float));

    // one warp per edge: NE warps = NE*32 threads, 256/block
    score_kernel<<<(NE * 32 + 255) / 256, 256>>>(q, k, attn, index);
    // one thread per (edge, head-half): NE*2 threads
    norm_kernel<<<(NE * 2 + 255) / 256, 256>>>(index, out);
}

// round 11
// speedup vs baseline: 1.1474x; 1.0463x over previous
#include <cuda_runtime.h>
#include <cstdint>

// Problem constants (fixed by dataset setup_inputs)
#define NE 400000          // edges
#define NH 8               // heads
#define ND 32              // head dim
#define MAX_NODES 50000    // n_nodes

#define EH (NE * NH)       // 3,200,000 (e,h) pairs
#define SEG (MAX_NODES * NH)

// Scratch (allocation-free rule: __device__ globals)
__device__ float g_score[EH];   // 12.8 MB  (holds exp(relu(dot)))
__device__ float g_sum[SEG];    // 1.6 MB   (per (node,head) sum of exps)

// ---------------------------------------------------------------------------
// 1) Warp-cooperative: warp w handles edge w, all 8 heads.
//    q/k loaded with __ldcs (evict-first streaming: touched exactly once) so
//    L2 retains g_score/g_sum lines for the norm pass.
// ---------------------------------------------------------------------------
__global__ void __launch_bounds__(256) score_kernel(
    const float* __restrict__ q,
    const float* __restrict__ k,
    const float* __restrict__ attn,
    const int*   __restrict__ index)
{
    __shared__ float4 s_attn[2 * NH * 8];   // 128 float4 = 2KB
    {
        const float4* a4 = (const float4*)attn;
        for (int i = threadIdx.x; i < NH * 16; i += blockDim.x) {
            int h = i >> 4;
            int j = i & 15;
            if (j < 8) s_attn[h * 8 + j] = a4[i];            // aq
            else       s_attn[64 + h * 8 + (j - 8)] = a4[i]; // ak
        }
    }
    __syncthreads();

    const int lane = threadIdx.x & 31;
    const int warp = (blockIdx.x * blockDim.x + threadIdx.x) >> 5;  // edge id
    if (warp >= NE) return;

    const int g = lane >> 3;          // group 0..3
    const int r = lane & 7;           // quad index within head

    const float4* __restrict__ q4 = (const float4*)q + (size_t)warp * 64;
    const float4* __restrict__ k4 = (const float4*)k + (size_t)warp * 64;

    float4 qa = __ldcs(q4 + lane);        // streaming, evict-first
    float4 qb = __ldcs(q4 + 32 + lane);
    float4 ka = __ldcs(k4 + lane);
    float4 kb = __ldcs(k4 + 32 + lane);

    float4 aq0 = s_attn[g * 8 + r];
    float4 aq1 = s_attn[(g + 4) * 8 + r];
    float4 ak0 = s_attn[64 + g * 8 + r];
    float4 ak1 = s_attn[64 + (g + 4) * 8 + r];

    float acc0 = qa.x * aq0.x;
    acc0 = fmaf(qa.y, aq0.y, acc0);
    acc0 = fmaf(qa.z, aq0.z, acc0);
    acc0 = fmaf(qa.w, aq0.w, acc0);
    acc0 = fmaf(ka.x, ak0.x, acc0);
    acc0 = fmaf(ka.y, ak0.y, acc0);
    acc0 = fmaf(ka.z, ak0.z, acc0);
    acc0 = fmaf(ka.w, ak0.w, acc0);

    float acc1 = qb.x * aq1.x;
    acc1 = fmaf(qb.y, aq1.y, acc1);
    acc1 = fmaf(qb.z, aq1.z, acc1);
    acc1 = fmaf(qb.w, aq1.w, acc1);
    acc1 = fmaf(kb.x, ak1.x, acc1);
    acc1 = fmaf(kb.y, ak1.y, acc1);
    acc1 = fmaf(kb.z, ak1.z, acc1);
    acc1 = fmaf(kb.w, ak1.w, acc1);

#pragma unroll
    for (int o = 4; o >= 1; o >>= 1) {
        acc0 += __shfl_xor_sync(0xFFFFFFFFu, acc0, o);
        acc1 += __shfl_xor_sync(0xFFFFFFFFu, acc1, o);
    }

    float e0 = __expf(fmaxf(acc0, 0.0f));   // head g     (valid on leaders)
    float e1 = __expf(fmaxf(acc1, 0.0f));   // head g + 4 (valid on leaders)

    int src = (lane & 3) * 8;
    float v_lo = __shfl_sync(0xFFFFFFFFu, e0, src);
    float v_hi = __shfl_sync(0xFFFFFFFFu, e1, src);

    bool lo = (lane < 4);
    bool hi = (lane >= 8 && lane < 12);
    if (lo | hi) {
        int head = (lane & 3) + (hi ? 4 : 0);
        float v  = hi ? v_hi : v_lo;
        int node = index[warp];                       // uniform within warp
        g_score[(size_t)warp * NH + head] = v;        // stays L2-resident
        atomicAdd(&g_sum[node * NH + head], v);       // L2 atomic
    }
}

// ---------------------------------------------------------------------------
// 2) out[e, 4h-half] = score / seg_sum — one thread per (edge, head-half).
//    score/sums read via L2 (mostly resident thanks to __ldcs streaming of
//    q/k above); out written streaming (never re-read).
// ---------------------------------------------------------------------------
__global__ void __launch_bounds__(256) norm_kernel(
    const int*  __restrict__ index,
    float*      __restrict__ out)
{
    // reverse block order: last-written score lines are the most L2-fresh
    int t = (gridDim.x - 1 - blockIdx.x) * blockDim.x + threadIdx.x;
    if (t >= NE * 2) return;

    int e    = t >> 1;          // edge
    int half = t & 1;           // 0: heads 0-3, 1: heads 4-7

    int node = index[e];
    float4 x = __ldcg((const float4*)g_score + (size_t)e * 2 + half);
    float4 d = __ldcg((const float4*)(g_sum + (size_t)node * NH) + half);

    float4 o;
    o.x = x.x / d.x;
    o.y = x.y / d.y;
    o.z = x.z / d.z;
    o.w = x.w / d.w;

    __stcs((float4*)out + (size_t)e * 2 + half, o);
}

// ---------------------------------------------------------------------------
extern "C" void kernel_launch(void* const* d_in, const int* in_sizes, int n_in,
                              void* d_out, int out_size)
{
    const float* q     = (const float*)d_in[0];
    const float* k     = (const float*)d_in[1];
    const float* attn  = (const float*)d_in[2];
    const int*   index = (const int*)d_in[3];
    float* out = (float*)d_out;

    (void)in_sizes; (void)n_in; (void)out_size;

    // Zero per-segment sums via a graph memset node.
    void* sum_ptr = nullptr;
    cudaGetSymbolAddress(&sum_ptr, g_sum);
    cudaMemsetAsync(sum_ptr, 0, (size_t)SEG * sizeof(float));

    // one warp per edge: NE warps = NE*32 threads, 256/block
    score_kernel<<<(NE * 32 + 255) / 256, 256>>>(q, k, attn, index);
    // one thread per (edge, head-half): NE*2 threads
    norm_kernel<<<(NE * 2 + 255) / 256, 256>>>(index, out);
}